// round 4
// baseline (speedup 1.0000x reference)
#include <cuda_runtime.h>
#include <cuda_bf16.h>
#include <cstdint>

// out[b][o] = sum_k x[b][k] * W[o][k] + bias[o]
// bf16-split mma.sync: D = xh*wh + xh*wl + xl*wh (fp32 accum, rel err ~4e-6).
// R4: single merged K-loop (frags loaded once per k-step, 3 HMMA groups) and
// smem-bounce epilogue (swizzled STS -> LDS.128 -> coalesced STG.128) to cut
// L1 wavefronts ~27% (L1 was the binding pipe at 78.4%).

#define THREADS 256
#define KDIM    128
#define TILE_B  128

#define XS_OFF(b,p) ((((b)*2)+(p))*32768)
#define WS_OFF(p)   (131072 + (p)*32768)
#define SMEM_BYTES  196608

// ---------------- helpers ----------------
__device__ __forceinline__ uint32_t smem_u32(const void* p) {
    uint32_t a;
    asm("{ .reg .u64 t; cvta.to.shared.u64 t, %1; cvt.u32.u64 %0, t; }" : "=r"(a) : "l"(p));
    return a;
}
__device__ __forceinline__ void sts64(uint32_t addr, uint32_t a, uint32_t b) {
    asm volatile("st.shared.v2.b32 [%0], {%1,%2};" :: "r"(addr), "r"(a), "r"(b));
}
__device__ __forceinline__ void sts64f(uint32_t addr, float a, float b) {
    asm volatile("st.shared.v2.f32 [%0], {%1,%2};" :: "r"(addr), "f"(a), "f"(b));
}
__device__ __forceinline__ void lds128f(float4& v, uint32_t addr) {
    asm volatile("ld.shared.v4.f32 {%0,%1,%2,%3}, [%4];"
                 : "=f"(v.x), "=f"(v.y), "=f"(v.z), "=f"(v.w) : "r"(addr));
}
__device__ __forceinline__ void ldsm4(uint32_t r[4], uint32_t addr) {
    asm volatile("ldmatrix.sync.aligned.m8n8.x4.shared.b16 {%0,%1,%2,%3}, [%4];"
                 : "=r"(r[0]), "=r"(r[1]), "=r"(r[2]), "=r"(r[3]) : "r"(addr));
}
__device__ __forceinline__ void hmma(float* d, const uint32_t a[4], uint32_t b0, uint32_t b1) {
    asm volatile("mma.sync.aligned.m16n8k16.row.col.f32.bf16.bf16.f32 "
                 "{%0,%1,%2,%3}, {%4,%5,%6,%7}, {%8,%9}, {%0,%1,%2,%3};"
                 : "+f"(d[0]), "+f"(d[1]), "+f"(d[2]), "+f"(d[3])
                 : "r"(a[0]), "r"(a[1]), "r"(a[2]), "r"(a[3]), "r"(b0), "r"(b1));
}
__device__ __forceinline__ void cvt_pair(float xx, float yy, uint32_t& h, uint32_t& l) {
    __nv_bfloat162 hb = __float22bfloat162_rn(make_float2(xx, yy));
    float2 hf = __bfloat1622float2(hb);
    __nv_bfloat162 lb = __float22bfloat162_rn(make_float2(xx - hf.x, yy - hf.y));
    h = *reinterpret_cast<uint32_t*>(&hb);
    l = *reinterpret_cast<uint32_t*>(&lb);
}
// bf16 tile swizzle: 128 rows x 256B
__device__ __forceinline__ uint32_t swz(int row, uint32_t kb) {
    return (uint32_t)row * 256u + (kb ^ (uint32_t)((row & 7) << 4));
}
// f32 epilogue scratch swizzle: 128 rows x 512B
__device__ __forceinline__ uint32_t eswz(int row, uint32_t colb) {
    return (uint32_t)row * 512u + (colb ^ (uint32_t)((row & 7) << 5));
}

__device__ __forceinline__ void ldg_batch(const float4* __restrict__ src, int tid, int j,
                                          float4 st[8]) {
    #pragma unroll
    for (int it = 0; it < 8; ++it) st[it] = src[tid + (j * 8 + it) * THREADS];
}
__device__ __forceinline__ void sts_batch(uint32_t xh, uint32_t xl, int tid, int j,
                                          const float4 st[8]) {
    #pragma unroll
    for (int it = 0; it < 8; ++it) {
        int fidx = tid + (j * 8 + it) * THREADS;
        int row = fidx >> 5;
        int g4  = fidx & 31;
        uint32_t off = swz(row, (uint32_t)(g4 * 8));
        uint32_t h0, l0, h1, l1;
        cvt_pair(st[it].x, st[it].y, h0, l0);
        cvt_pair(st[it].z, st[it].w, h1, l1);
        sts64(xh + off, h0, h1);
        sts64(xl + off, l0, l1);
    }
}

__global__ __launch_bounds__(THREADS, 1)
void linear128_mma_kernel(const float* __restrict__ x,
                          const float* __restrict__ W,
                          const float* __restrict__ bias,
                          float* __restrict__ out,
                          int ntiles)
{
    extern __shared__ __align__(1024) char smem[];
    const uint32_t sb  = smem_u32(smem);
    const uint32_t wsh = sb + WS_OFF(0);
    const uint32_t wsl = sb + WS_OFF(1);

    const int tid  = threadIdx.x;
    const int lane = tid & 31;
    const int wid  = tid >> 5;
    const int mg   = wid >> 1;   // 0..3: batch rows 32*mg
    const int ng   = wid & 1;    // 0..1: out cols 64*ng

    // ---- stage W hi/lo into smem (once) ----
    {
        const float4* W4 = (const float4*)W;
        #pragma unroll
        for (int it = 0; it < 16; ++it) {
            int fidx = tid + it * THREADS;
            int row = fidx >> 5;
            int g4  = fidx & 31;
            float4 v = W4[fidx];
            uint32_t off = swz(row, (uint32_t)(g4 * 8));
            uint32_t h0, l0, h1, l1;
            cvt_pair(v.x, v.y, h0, l0);
            cvt_pair(v.z, v.w, h1, l1);
            sts64(wsh + off, h0, h1);
            sts64(wsl + off, l0, l1);
        }
    }

    // ---- bias fragment (float2 per nfrag; added before the smem bounce) ----
    float2 bv[8];
    #pragma unroll
    for (int nf = 0; nf < 8; ++nf)
        bv[nf] = *(const float2*)(bias + ng * 64 + nf * 8 + (lane & 3) * 2);

    // ---- per-thread ldmatrix address components ----
    uint32_t a_ro[2], a_sw[2];
    #pragma unroll
    for (int mf = 0; mf < 2; ++mf) {
        int r = mg * 32 + mf * 16 + ((lane >> 3) & 1) * 8 + (lane & 7);
        a_ro[mf] = (uint32_t)r * 256u;
        a_sw[mf] = (uint32_t)((r & 7) << 4);
    }
    const uint32_t a_kb = (uint32_t)((lane >> 4) * 16);
    uint32_t b_ro[4], b_sw[4];
    #pragma unroll
    for (int q = 0; q < 4; ++q) {
        int r = ng * 64 + q * 16 + ((lane >> 4) << 3) + (lane & 7);
        b_ro[q] = (uint32_t)r * 256u;
        b_sw[q] = (uint32_t)((r & 7) << 4);
    }
    const uint32_t b_kb = (uint32_t)(((lane >> 3) & 1) * 16);

    const int bid  = blockIdx.x;
    const int grid = gridDim.x;
    const float4* x4 = (const float4*)x;

    // ---- prologue: stage x tile(bid) into buf 0 ----
    if (bid < ntiles) {
        float4 st[8];
        ldg_batch(x4 + (size_t)bid * 4096, tid, 0, st);
        sts_batch(sb + XS_OFF(0, 0), sb + XS_OFF(0, 1), tid, 0, st);
        ldg_batch(x4 + (size_t)bid * 4096, tid, 1, st);
        sts_batch(sb + XS_OFF(0, 0), sb + XS_OFF(0, 1), tid, 1, st);
    }
    __syncthreads();

    int i = 0;
    for (int tile = bid; tile < ntiles; tile += grid, ++i) {
        const int b = i & 1;
        const uint32_t xh  = sb + XS_OFF(b, 0);
        const uint32_t xl  = sb + XS_OFF(b, 1);
        const uint32_t nxh = sb + XS_OFF(1 - b, 0);
        const uint32_t nxl = sb + XS_OFF(1 - b, 1);
        const bool hn = (tile + grid) < ntiles;
        const float4* nsrc = x4 + (size_t)(tile + grid) * 4096;

        float d[2][8][4];
        #pragma unroll
        for (int mf = 0; mf < 2; ++mf)
            #pragma unroll
            for (int nf = 0; nf < 8; ++nf)
                #pragma unroll
                for (int e = 0; e < 4; ++e) d[mf][nf][e] = 0.0f;

        float4 st[8];
        if (hn) ldg_batch(nsrc, tid, 0, st);

        // ---- merged K loop: frags loaded once per k-step, 3 HMMA groups ----
        #pragma unroll
        for (int ks = 0; ks < 8; ++ks) {
            const uint32_t kbyte = (uint32_t)(ks * 32);
            uint32_t ah[2][4], al[2][4];
            #pragma unroll
            for (int mf = 0; mf < 2; ++mf) {
                const uint32_t aoff = a_ro[mf] + ((kbyte + a_kb) ^ a_sw[mf]);
                ldsm4(ah[mf], xh + aoff);
                ldsm4(al[mf], xl + aoff);
            }
            uint32_t bh0[8], bh1[8], bl0[8], bl1[8];
            #pragma unroll
            for (int q = 0; q < 4; ++q) {
                const uint32_t boff = b_ro[q] + ((kbyte + b_kb) ^ b_sw[q]);
                uint32_t r[4];
                ldsm4(r, wsh + boff);
                bh0[2*q] = r[0]; bh1[2*q] = r[1]; bh0[2*q+1] = r[2]; bh1[2*q+1] = r[3];
                ldsm4(r, wsl + boff);
                bl0[2*q] = r[0]; bl1[2*q] = r[1]; bl0[2*q+1] = r[2]; bl1[2*q+1] = r[3];
            }
            #pragma unroll
            for (int mf = 0; mf < 2; ++mf)
                #pragma unroll
                for (int nf = 0; nf < 8; ++nf) {
                    hmma(d[mf][nf], ah[mf], bh0[nf], bh1[nf]);  // xh*wh
                    hmma(d[mf][nf], ah[mf], bl0[nf], bl1[nf]);  // xh*wl
                    hmma(d[mf][nf], al[mf], bh0[nf], bh1[nf]);  // xl*wh
                }
            if (ks == 3 && hn) { sts_batch(nxh, nxl, tid, 0, st); ldg_batch(nsrc, tid, 1, st); }
            if (ks == 5 && hn) { sts_batch(nxh, nxl, tid, 1, st); }
        }

        __syncthreads();   // all warps done reading buf b (and staging buf 1-b)

        // ---- epilogue via smem bounce: reuse buf b (64KB) as f32 scratch ----
        const uint32_t scr = sb + XS_OFF(b, 0);
        #pragma unroll
        for (int mf = 0; mf < 2; ++mf) {
            const int r0 = mg * 32 + mf * 16 + (lane >> 2);
            #pragma unroll
            for (int nf = 0; nf < 8; ++nf) {
                const uint32_t colb = (uint32_t)((ng * 64 + nf * 8 + (lane & 3) * 2) * 4);
                sts64f(scr + eswz(r0,     colb), d[mf][nf][0] + bv[nf].x, d[mf][nf][1] + bv[nf].y);
                sts64f(scr + eswz(r0 + 8, colb), d[mf][nf][2] + bv[nf].x, d[mf][nf][3] + bv[nf].y);
            }
        }
        __syncthreads();

        // coalesced readback + STG.128 (each warp owns 16 rows)
        {
            float* outp = out + (size_t)tile * TILE_B * 128;
            #pragma unroll
            for (int j = 0; j < 4; ++j) {
                const int row = wid * 16 + j * 4 + (lane >> 3);
                #pragma unroll
                for (int sub = 0; sub < 4; ++sub) {
                    const uint32_t colb = (uint32_t)(sub * 128 + (lane & 7) * 16);
                    float4 v;
                    lds128f(v, scr + eswz(row, colb));
                    *(float4*)(outp + (size_t)row * 128 + (colb >> 2)) = v;
                }
            }
        }
        __syncthreads();   // scratch reads done before next staging overwrites buf b
    }
}

extern "C" void kernel_launch(void* const* d_in, const int* in_sizes, int n_in,
                              void* d_out, int out_size)
{
    const float* x    = (const float*)d_in[0];
    const float* W    = (const float*)d_in[1];
    const float* bias = (const float*)d_in[2];
    float* out = (float*)d_out;

    const int batch  = in_sizes[0] / KDIM;   // 1048576
    const int ntiles = batch / TILE_B;       // 8192

    int sms = 148;
    cudaDeviceGetAttribute(&sms, cudaDevAttrMultiProcessorCount, 0);
    if (sms <= 0) sms = 148;
    int grid = sms < ntiles ? sms : ntiles;

    cudaFuncSetAttribute(linear128_mma_kernel,
                         cudaFuncAttributeMaxDynamicSharedMemorySize, SMEM_BYTES);

    linear128_mma_kernel<<<grid, THREADS, SMEM_BYTES>>>(x, W, bias, out, ntiles);
}